// round 4
// baseline (speedup 1.0000x reference)
#include <cuda_runtime.h>
#include <cuda_bf16.h>
#include <cstdint>

// ============================================================================
// Problem constants
// ============================================================================
#define DGRID 128
#define D3 (DGRID * DGRID * DGRID)
#define MCAP 100096              // capacity (multiple of 128) >= M
#define NCH 64

// ============================================================================
// Device globals (scratch — no allocation allowed)
// ============================================================================
__device__ int g_lookup[D3];
__device__ int g_nbr[27 * MCAP];
__device__ __align__(16) __nv_bfloat16 g_xh[(MCAP + 1) * NCH];
__device__ __align__(16) __nv_bfloat16 g_xl[(MCAP + 1) * NCH];
__device__ __align__(16) __nv_bfloat16 g_hh[(MCAP + 1) * NCH];
__device__ __align__(16) __nv_bfloat16 g_hl[(MCAP + 1) * NCH];
__device__ __align__(16) __nv_bfloat16 g_w1h[27 * NCH * NCH];
__device__ __align__(16) __nv_bfloat16 g_w1l[27 * NCH * NCH];
__device__ __align__(16) __nv_bfloat16 g_w2h[27 * NCH * NCH];
__device__ __align__(16) __nv_bfloat16 g_w2l[27 * NCH * NCH];

// ============================================================================
// Small PTX helpers (all baseline PTX, no sm_103a-only features)
// ============================================================================
__device__ __forceinline__ uint32_t sw128(uint32_t off) {
    return off ^ ((off >> 3) & 0x70);
}

__device__ __forceinline__ void cp16(uint32_t smem_addr, const void* gptr) {
    asm volatile("cp.async.cg.shared.global [%0], [%1], 16;"
                 :: "r"(smem_addr), "l"(__cvta_generic_to_global(gptr)));
}

#define CP_COMMIT() asm volatile("cp.async.commit_group;" ::: "memory")
#define CP_WAIT(N)  asm volatile("cp.async.wait_group %0;" :: "n"(N) : "memory")

__device__ __forceinline__ void ldmat_x4(uint32_t* r, uint32_t addr) {
    asm volatile("ldmatrix.sync.aligned.m8n8.x4.shared.b16 {%0,%1,%2,%3}, [%4];"
                 : "=r"(r[0]), "=r"(r[1]), "=r"(r[2]), "=r"(r[3]) : "r"(addr));
}

__device__ __forceinline__ void mma_bf16(float* d, const uint32_t* a,
                                         uint32_t b0, uint32_t b1) {
    asm volatile(
        "mma.sync.aligned.m16n8k16.row.col.f32.bf16.bf16.f32 "
        "{%0,%1,%2,%3}, {%4,%5,%6,%7}, {%8,%9}, {%0,%1,%2,%3};"
        : "+f"(d[0]), "+f"(d[1]), "+f"(d[2]), "+f"(d[3])
        : "r"(a[0]), "r"(a[1]), "r"(a[2]), "r"(a[3]), "r"(b0), "r"(b1));
}

// ============================================================================
// Prep kernels
// ============================================================================
__global__ void k_init_lookup() {
    int i = blockIdx.x * blockDim.x + threadIdx.x;
    if (i < D3) g_lookup[i] = -1;
}

__global__ void k_scatter(const int* __restrict__ coords, int M) {
    int i = blockIdx.x * blockDim.x + threadIdx.x;
    if (i >= M) return;
    int c0 = coords[3 * i], c1 = coords[3 * i + 1], c2 = coords[3 * i + 2];
    g_lookup[(c0 * DGRID + c1) * DGRID + c2] = i;
}

__global__ void k_build_nbr(const int* __restrict__ coords, int M) {
    int i = blockIdx.x * blockDim.x + threadIdx.x;
    if (i >= M) return;
    int c0 = coords[3 * i], c1 = coords[3 * i + 1], c2 = coords[3 * i + 2];
#pragma unroll
    for (int t = 0; t < 27; t++) {
        int dx = t / 9 - 1, dy = (t / 3) % 3 - 1, dz = t % 3 - 1;
        int x = c0 + dx, y = c1 + dy, z = c2 + dz;
        int idx = M;  // zero row for invalid neighbors
        if (x >= 0 && x < DGRID && y >= 0 && y < DGRID && z >= 0 && z < DGRID) {
            int j = g_lookup[(x * DGRID + y) * DGRID + z];
            if (j >= 0) idx = j;
        }
        g_nbr[t * MCAP + i] = idx;
    }
}

__global__ void k_convert_x(const float* __restrict__ feats, int M) {
    int idx = blockIdx.x * blockDim.x + threadIdx.x;
    int total = (M + 1) * NCH;
    if (idx >= total) return;
    float v = (idx < M * NCH) ? feats[idx] : 0.0f;  // row M = zeros
    __nv_bfloat16 hi = __float2bfloat16(v);
    float r = v - __bfloat162float(hi);
    g_xh[idx] = hi;
    g_xl[idx] = __float2bfloat16(r);
}

__global__ void k_zero_hrow(int M) {
    int t = threadIdx.x;
    if (t < NCH) {
        g_hh[(size_t)M * NCH + t] = __float2bfloat16(0.0f);
        g_hl[(size_t)M * NCH + t] = __float2bfloat16(0.0f);
    }
}

// W[t][j][c] (f32) -> Wt[t][c][j] split into bf16 hi/lo ([n][k] rows for .col B)
template <int L>
__global__ void k_convert_w(const float* __restrict__ W) {
    int idx = blockIdx.x * blockDim.x + threadIdx.x;
    if (idx >= 27 * NCH * NCH) return;
    int t = idx >> 12;
    int r = idx & 4095;
    int c = r >> 6;   // n index (output channel)
    int j = r & 63;   // k index (input channel)
    float w = W[(t << 12) + (j << 6) + c];
    __nv_bfloat16 hi = __float2bfloat16(w);
    float res = w - __bfloat162float(hi);
    __nv_bfloat16 lo = __float2bfloat16(res);
    if (L == 0) { g_w1h[idx] = hi; g_w1l[idx] = lo; }
    else        { g_w2h[idx] = hi; g_w2l[idx] = lo; }
}

// ============================================================================
// Conv layer kernel: mma.sync bf16 split, cp.async 2-stage pipeline
// 128 rows x 64 cols per CTA, 256 threads (8 warps x 16 rows)
// ============================================================================
#define SMEM_BIAS  0
#define SMEM_DATA  1024
#define A_H_OFF    0
#define A_L_OFF    16384
#define W_H_OFF    32768
#define W_L_OFF    40960
#define BUFSZ      49152
#define SMEM_TOTAL (SMEM_DATA + 2 * BUFSZ)   // 99328 bytes

template <int LAYER>
__global__ void __launch_bounds__(256, 2)
conv_kernel(const float* __restrict__ bias, float* __restrict__ out, int M) {
    extern __shared__ __align__(1024) char smem[];
    const int tid  = threadIdx.x;
    const int warp = tid >> 5;
    const int lane = tid & 31;
    uint32_t sb;
    asm("{ .reg .u64 t; cvta.to.shared.u64 t, %1; cvt.u32.u64 %0, t; }"
        : "=r"(sb) : "l"(smem));

    const __nv_bfloat16* __restrict__ Xh  = (LAYER == 0) ? g_xh  : g_hh;
    const __nv_bfloat16* __restrict__ Xl  = (LAYER == 0) ? g_xl  : g_hl;
    const __nv_bfloat16* __restrict__ Wh0 = (LAYER == 0) ? g_w1h : g_w2h;
    const __nv_bfloat16* __restrict__ Wl0 = (LAYER == 0) ? g_w1l : g_w2l;

    const int row0 = blockIdx.x * 128;

    if (tid < NCH) ((float*)(smem + SMEM_BIAS))[tid] = bias[tid];

    // ---- per-thread load geometry ----
    const int rr   = tid >> 1;           // 0..127 (A row within tile)
    const int half = tid & 1;            // 0..1  (64-byte half of a 128B row)
    const int wc0  = tid * 2;            // W chunk base (2 chunks per thread)
    const bool rvalid = (row0 + rr) < M;

    // fetch neighbor index for offset k (this thread's A row)
    auto nbr_idx = [&](int k) -> int {
        return rvalid ? g_nbr[k * MCAP + row0 + rr] : M;
    };

    // issue one stage of cp.async loads with a pre-resolved gather index
    auto issue_load = [&](int k, uint32_t buf, int idx) {
        const char* srch = (const char*)(Xh + (size_t)idx * NCH) + half * 64;
        const char* srcl = (const char*)(Xl + (size_t)idx * NCH) + half * 64;
#pragma unroll
        for (int c = 0; c < 4; c++) {
            uint32_t so = sw128((uint32_t)(rr * 128 + half * 64 + c * 16));
            cp16(buf + A_H_OFF + so, srch + c * 16);
            cp16(buf + A_L_OFF + so, srcl + c * 16);
        }
        const char* wsh = (const char*)(Wh0 + (size_t)k * 4096);
        const char* wsl = (const char*)(Wl0 + (size_t)k * 4096);
#pragma unroll
        for (int q = 0; q < 2; q++) {
            int c = wc0 + q;
            uint32_t off = (uint32_t)(c * 16);     // wr*128 + wchunk*16
            uint32_t so = sw128(off);
            cp16(buf + W_H_OFF + so, wsh + off);
            cp16(buf + W_L_OFF + so, wsl + off);
        }
    };

    // ---- accumulators, bias preloaded ----
    float acc[8][4];

    // prologue
    issue_load(0, sb + SMEM_DATA, nbr_idx(0));
    CP_COMMIT();
    issue_load(1, sb + SMEM_DATA + BUFSZ, nbr_idx(1));
    CP_COMMIT();
    int nidx = nbr_idx(2);   // prefetched gather index for k+2
    __syncthreads();  // bias visible

    {
        const float* sbias = (const float*)(smem + SMEM_BIAS);
#pragma unroll
        for (int nt = 0; nt < 8; nt++) {
            int n = nt * 8 + (lane & 3) * 2;
            float b0 = sbias[n], b1 = sbias[n + 1];
            acc[nt][0] = b0; acc[nt][1] = b1; acc[nt][2] = b0; acc[nt][3] = b1;
        }
    }

    // ---- fragment address geometry ----
    const uint32_t a_row  = (uint32_t)(warp * 16 + (lane & 15));
    const uint32_t a_koff = (uint32_t)((lane >> 4) << 4);          // 0 / 16
    const uint32_t b_row  = (uint32_t)((lane & 7) + ((lane >> 4) << 3)); // 0..15
    const uint32_t b_koff = (uint32_t)(((lane >> 3) & 1) << 4);    // 0 / 16

    for (int k = 0; k < 27; k++) {
        // prefetch next gather index early — a full iteration of MMA work
        // hides the nbr-load latency before issue_load consumes it
        int nidx_next = (k + 3 < 27) ? nbr_idx(k + 3) : M;

        const uint32_t buf = sb + SMEM_DATA + (uint32_t)(k & 1) * BUFSZ;
        CP_WAIT(1);
        __syncthreads();

        // A fragments for this warp's 16 rows (hi & lo), 4 k-steps
        uint32_t a_h[4][4], a_l[4][4];
#pragma unroll
        for (int kk = 0; kk < 4; kk++) {
            uint32_t so = sw128(a_row * 128 + (uint32_t)kk * 32 + a_koff);
            ldmat_x4(a_h[kk], buf + A_H_OFF + so);
            ldmat_x4(a_l[kk], buf + A_L_OFF + so);
        }

        // B fragments + MMAs: 4 n-tile pairs x 4 k-steps x (hh, hl, lh)
#pragma unroll
        for (int p = 0; p < 4; p++) {
#pragma unroll
            for (int kk = 0; kk < 4; kk++) {
                uint32_t so = sw128(((uint32_t)(p * 16) + b_row) * 128 +
                                    (uint32_t)kk * 32 + b_koff);
                uint32_t bh[4], bl[4];
                ldmat_x4(bh, buf + W_H_OFF + so);
                ldmat_x4(bl, buf + W_L_OFF + so);
                mma_bf16(acc[2 * p],     a_h[kk], bh[0], bh[1]);
                mma_bf16(acc[2 * p + 1], a_h[kk], bh[2], bh[3]);
                mma_bf16(acc[2 * p],     a_h[kk], bl[0], bl[1]);
                mma_bf16(acc[2 * p + 1], a_h[kk], bl[2], bl[3]);
                mma_bf16(acc[2 * p],     a_l[kk], bh[0], bh[1]);
                mma_bf16(acc[2 * p + 1], a_l[kk], bh[2], bh[3]);
            }
        }

        __syncthreads();   // all warps done reading buf before refill
        if (k + 2 < 27) issue_load(k + 2, buf, nidx);
        CP_COMMIT();       // keep group accounting uniform
        nidx = nidx_next;
    }

    // ---- epilogue: ReLU (+ bias already in acc), store ----
    const int m0 = row0 + warp * 16 + (lane >> 2);
    const int m1 = m0 + 8;
    if (LAYER == 0) {
        uint32_t* hhp = (uint32_t*)g_hh;
        uint32_t* hlp = (uint32_t*)g_hl;
#pragma unroll
        for (int nt = 0; nt < 8; nt++) {
            int n = nt * 8 + (lane & 3) * 2;
#pragma unroll
            for (int rpair = 0; rpair < 2; rpair++) {
                int m = rpair ? m1 : m0;
                if (m < M) {
                    float v0 = fmaxf(acc[nt][2 * rpair],     0.0f);
                    float v1 = fmaxf(acc[nt][2 * rpair + 1], 0.0f);
                    __nv_bfloat16 h0 = __float2bfloat16(v0);
                    __nv_bfloat16 h1 = __float2bfloat16(v1);
                    __nv_bfloat16 l0 = __float2bfloat16(v0 - __bfloat162float(h0));
                    __nv_bfloat16 l1 = __float2bfloat16(v1 - __bfloat162float(h1));
                    hhp[m * 32 + n / 2] =
                        (uint32_t)__bfloat16_as_ushort(h0) |
                        ((uint32_t)__bfloat16_as_ushort(h1) << 16);
                    hlp[m * 32 + n / 2] =
                        (uint32_t)__bfloat16_as_ushort(l0) |
                        ((uint32_t)__bfloat16_as_ushort(l1) << 16);
                }
            }
        }
    } else {
#pragma unroll
        for (int nt = 0; nt < 8; nt++) {
            int n = nt * 8 + (lane & 3) * 2;
#pragma unroll
            for (int rpair = 0; rpair < 2; rpair++) {
                int m = rpair ? m1 : m0;
                if (m < M) {
                    float2 v;
                    v.x = fmaxf(acc[nt][2 * rpair],     0.0f);
                    v.y = fmaxf(acc[nt][2 * rpair + 1], 0.0f);
                    *(float2*)(out + (size_t)m * NCH + n) = v;
                }
            }
        }
    }
}

// ============================================================================
// Launch
// ============================================================================
extern "C" void kernel_launch(void* const* d_in, const int* in_sizes, int n_in,
                              void* d_out, int out_size) {
    const float* feats  = (const float*)d_in[0];
    const float* W1     = (const float*)d_in[1];
    const float* b1     = (const float*)d_in[2];
    const float* W2     = (const float*)d_in[3];
    const float* b2     = (const float*)d_in[4];
    const int*   coords = (const int*)d_in[5];
    const int M = in_sizes[0] / NCH;

    cudaFuncSetAttribute(conv_kernel<0>,
                         cudaFuncAttributeMaxDynamicSharedMemorySize, SMEM_TOTAL);
    cudaFuncSetAttribute(conv_kernel<1>,
                         cudaFuncAttributeMaxDynamicSharedMemorySize, SMEM_TOTAL);

    k_init_lookup<<<(D3 + 511) / 512, 512>>>();
    k_scatter<<<(M + 255) / 256, 256>>>(coords, M);
    k_build_nbr<<<(M + 255) / 256, 256>>>(coords, M);
    k_convert_x<<<((M + 1) * NCH + 255) / 256, 256>>>(feats, M);
    k_convert_w<0><<<(27 * NCH * NCH + 255) / 256, 256>>>(W1);
    k_convert_w<1><<<(27 * NCH * NCH + 255) / 256, 256>>>(W2);
    k_zero_hrow<<<1, 64>>>(M);

    const int nblk = (M + 127) / 128;
    conv_kernel<0><<<nblk, 256, SMEM_TOTAL>>>(b1, nullptr, M);
    conv_kernel<1><<<nblk, 256, SMEM_TOTAL>>>(b2, (float*)d_out, M);
}